// round 15
// baseline (speedup 1.0000x reference)
#include <cuda_runtime.h>

#define BB 256
#define TT 512
#define KK 128

// ---- scratch (no allocations allowed) ----
__device__ float g_v[(long)BB * TT * KK];   // 64MB: viterbi values per (b,t,k)
__device__ float g_transT[KK * KK];         // transT[c*K+j] = trans[j*K+c]
__device__ int   g_order[BB];               // batches sorted by length desc
__device__ float g_lognorm[BB];
__device__ float g_gold[BB];                // gold-path score (lognorm subtracted later)
__device__ int   g_correct[BB];
__device__ int   g_total[BB];

// ---- packed f32x2 helpers (sm_103a): add/fma only ----
__device__ __forceinline__ unsigned long long f2pack(float a, float b) {
    unsigned long long r;
    asm("mov.b64 %0, {%1,%2};" : "=l"(r) : "f"(a), "f"(b));
    return r;
}
__device__ __forceinline__ void f2unpack(unsigned long long v, float& a, float& b) {
    asm("mov.b64 {%0,%1}, %2;" : "=f"(a), "=f"(b) : "l"(v));
}
__device__ __forceinline__ unsigned long long f2add(unsigned long long a, unsigned long long b) {
    unsigned long long r;
    asm("add.rn.f32x2 %0, %1, %2;" : "=l"(r) : "l"(a), "l"(b));
    return r;
}
__device__ __forceinline__ unsigned long long f2fma(unsigned long long a, unsigned long long b,
                                                    unsigned long long c) {
    unsigned long long r;
    asm("fma.rn.f32x2 %0, %1, %2, %3;" : "=l"(r) : "l"(a), "l"(b), "l"(c));
    return r;
}

// warp argmax over (packed 4-per-lane) candidates: returns global index 0..127.
// key = ordered-uint map of the lane-local best value; bi its local sub-index.
__device__ __forceinline__ int warp_argmax_idx(unsigned key, int bi)
{
    unsigned mx = key;
    #pragma unroll
    for (int o = 16; o > 0; o >>= 1) {           // shfl butterfly max
        unsigned ok = __shfl_xor_sync(0xffffffffu, mx, o);
        mx = (ok > mx) ? ok : mx;
    }
    unsigned ball = __ballot_sync(0xffffffffu, key == mx);
    int src = __ffs(ball) - 1;
    return (src << 2) + __shfl_sync(0xffffffffu, bi, src);
}

__device__ __forceinline__ float pick4(float4 q, int sub)
{
    float a = (sub & 1) ? q.y : q.x;
    float b = (sub & 1) ? q.w : q.z;
    return (sub & 2) ? b : a;
}

// ============================================================
// Kernel 0: prep = LPT sort (block 0) + transpose (blocks 1..128).
// ============================================================
__global__ __launch_bounds__(256)
void prep_kernel(const int* __restrict__ lengths, const float* __restrict__ trans)
{
    if (blockIdx.x == 0) {
        __shared__ int keys[BB];
        int b = threadIdx.x;
        int key = (lengths[b] << 8) | (BB - 1 - b);
        keys[b] = key;
        __syncthreads();
        int r = 0;
        #pragma unroll 8
        for (int j = 0; j < BB; j++) r += (keys[j] > key);
        g_order[r] = b;
    } else {
        int c = blockIdx.x - 1;
        int j = threadIdx.x;
        if (j < KK) g_transT[c * KK + j] = trans[j * KK + c];
    }
}

// ============================================================
// Kernel 1: fused scans + backtrack, early exit at t = len.
// Blocks [0,256): Viterbi forward (values) THEN warp-0 chase
// using exact-match backpointer recovery, THEN epilogue.
// Blocks [256,512): CRF forward (exp-domain logsumexp).
// ============================================================
__global__ __launch_bounds__(128)
void crf_scan_kernel(const float* __restrict__ emissions,
                     const int*   __restrict__ tag_ids,
                     const int*   __restrict__ lengths,
                     const float* __restrict__ trans,
                     float*       __restrict__ out)
{
    __shared__ ulonglong2 bufP[2][KK / 4];   // packed state vector (double buffer)
    __shared__ float      redS[2][4];
    __shared__ int        tagS[TT];
    __shared__ int        iredS[4];

    const int k    = threadIdx.x;
    const int role = (blockIdx.x >= BB);
    const int b    = g_order[role ? (blockIdx.x - BB) : blockIdx.x];
    const int len  = lengths[b];
    const float* em = emissions + (long)b * TT * KK;
    const int wid = k >> 5, lane = k & 31;

    if (!role) {
        // -------- Viterbi forward: packed adds, scalar max, t < len --------
        unsigned long long trp[KK / 2];      // packed transition column k
        #pragma unroll
        for (int m = 0; m < KK / 2; m++)
            trp[m] = f2pack(trans[(2 * m) * KK + k], trans[(2 * m + 1) * KK + k]);

        float* vglob = g_v + (long)b * TT * KK;

        float v = em[k];                     // t = 0
        vglob[k] = v;
        int buf = 0;
        ((float*)bufP[0])[k] = v;
        __syncthreads();

        float emit = em[KK + k];             // prefetch t = 1
        for (int t = 1; t < len; t++) {
            float emit_next = (t + 1 < TT) ? em[(t + 1) * KK + k] : 0.0f;

            float b0 = -3.4e38f, b1 = -3.4e38f, b2 = -3.4e38f, b3 = -3.4e38f;
            #pragma unroll
            for (int jj = 0; jj < KK / 4; jj++) {
                ulonglong2 q = bufP[buf][jj];
                float x0, x1, x2, x3;
                f2unpack(f2add(q.x, trp[2 * jj]),     x0, x1);
                f2unpack(f2add(q.y, trp[2 * jj + 1]), x2, x3);
                b0 = fmaxf(b0, x0); b1 = fmaxf(b1, x1);
                b2 = fmaxf(b2, x2); b3 = fmaxf(b3, x3);
            }
            v = fmaxf(fmaxf(b0, b1), fmaxf(b2, b3)) + emit;
            vglob[t * KK + k] = v;

            ((float*)bufP[buf ^ 1])[k] = v;
            __syncthreads();
            buf ^= 1;
            emit = emit_next;
        }

        // ==== backtrack chase (warp 0): exact-match bp recovery ====
        if (wid == 0) {
            const int t0 = len - 1;
            const float* vb = vglob;

            // warm transT into L1 (independent float4 loads)
            float wsum = 0.f;
            const float4* tT4 = (const float4*)g_transT;
            #pragma unroll 4
            for (int i = lane; i < KK * KK / 4; i += 32) {
                float4 w4 = __ldg(tT4 + i);
                wsum += w4.x + w4.y + w4.z + w4.w;
            }

            // last_tag = argmax of final row (in smem bufP[buf])
            float4 q = ((const float4*)bufP[buf])[lane];
            float bv = q.x; int bi = 0;
            bool s1 = (q.y > bv); bi = s1 ? 1 : bi; bv = s1 ? q.y : bv;
            bool s2 = (q.z > bv); bi = s2 ? 2 : bi; bv = s2 ? q.z : bv;
            bool s3 = (q.w > bv); bi = s3 ? 3 : bi; bv = s3 ? q.w : bv;
            unsigned key = __float_as_uint(bv);
            key ^= ((unsigned)((int)key >> 31)) | 0x80000000u;
            if (wsum == -1.2345e38f) key = 0;        // keep warm loads alive
            int cur = warp_argmax_idx(key, bi);

            // tail fill [t0, TT)
            for (int t = t0 + lane; t < TT; t += 32) tagS[t] = cur;

            // current-row registers (row t) and prefetch rings (rows t-1-u)
            float4 vrow_t = q;                                // v row t0
            float4 emrow_t = __ldg((const float4*)(em + (long)t0 * KK) + lane);
            float4 vring[4], ering[4];
            #pragma unroll
            for (int u = 0; u < 4; u++) {
                int r = t0 - 1 - u; r = (r > 0) ? r : 0;
                vring[u] = __ldcs((const float4*)(vb + (long)r * KK) + lane);
                ering[u] = __ldg((const float4*)(em + (long)r * KK) + lane);
            }

            int t = t0;
            while (t >= 5) {
                #pragma unroll
                for (int u = 0; u < 4; u++) {
                    float4 vm1 = vring[u], em1 = ering[u];      // row t-1
                    int nr = t - 5 - u; nr = (nr > 0) ? nr : 0;
                    vring[u] = __ldcs((const float4*)(vb + (long)nr * KK) + lane);
                    ering[u] = __ldg((const float4*)(em + (long)nr * KK) + lane);

                    float4 tc4 = __ldg((const float4*)(g_transT + (cur << 7)) + lane);
                    int sub = cur & 3, srcl = cur >> 2;
                    float vcur = __shfl_sync(0xffffffffu, pick4(vrow_t, sub), srcl);
                    float ecur = __shfl_sync(0xffffffffu, pick4(emrow_t, sub), srcl);

                    float w0 = vm1.x + tc4.x, w1 = vm1.y + tc4.y;
                    float w2 = vm1.z + tc4.z, w3 = vm1.w + tc4.w;
                    bool m0 = (w0 + ecur) == vcur, m1 = (w1 + ecur) == vcur;
                    bool m2 = (w2 + ecur) == vcur, m3 = (w3 + ecur) == vcur;
                    int nm = (int)m0 + (int)m1 + (int)m2 + (int)m3;
                    int li = m0 ? 0 : (m1 ? 1 : (m2 ? 2 : 3));
                    unsigned ball  = __ballot_sync(0xffffffffu, nm > 0);
                    unsigned multi = __ballot_sync(0xffffffffu, nm > 1);
                    if (multi == 0u && __popc(ball) == 1) {      // unique match
                        int src = __ffs(ball) - 1;
                        cur = (src << 2) + __shfl_sync(0xffffffffu, li, src);
                    } else {                                     // rare: exact argmax
                        float lb = w0; int lj = 0;
                        bool h1 = (w1 > lb); lj = h1 ? 1 : lj; lb = h1 ? w1 : lb;
                        bool h2 = (w2 > lb); lj = h2 ? 2 : lj; lb = h2 ? w2 : lb;
                        bool h3 = (w3 > lb); lj = h3 ? 3 : lj; lb = h3 ? w3 : lb;
                        unsigned k2 = __float_as_uint(lb);
                        k2 ^= ((unsigned)((int)k2 >> 31)) | 0x80000000u;
                        cur = warp_argmax_idx(k2, lj);
                    }
                    if (lane == 0) tagS[t - u - 1] = cur;
                    vrow_t = vm1; emrow_t = em1;
                }
                t -= 4;
            }
            for (; t >= 1; t--) {                               // short tail
                float4 vm1 = __ldcs((const float4*)(vb + (long)(t - 1) * KK) + lane);
                float4 em1 = __ldg((const float4*)(em + (long)(t - 1) * KK) + lane);
                float4 tc4 = __ldg((const float4*)(g_transT + (cur << 7)) + lane);
                int sub = cur & 3, srcl = cur >> 2;
                float vcur = __shfl_sync(0xffffffffu, pick4(vrow_t, sub), srcl);
                float ecur = __shfl_sync(0xffffffffu, pick4(emrow_t, sub), srcl);
                float w0 = vm1.x + tc4.x, w1 = vm1.y + tc4.y;
                float w2 = vm1.z + tc4.z, w3 = vm1.w + tc4.w;
                bool m0 = (w0 + ecur) == vcur, m1 = (w1 + ecur) == vcur;
                bool m2 = (w2 + ecur) == vcur, m3 = (w3 + ecur) == vcur;
                int nm = (int)m0 + (int)m1 + (int)m2 + (int)m3;
                int li = m0 ? 0 : (m1 ? 1 : (m2 ? 2 : 3));
                unsigned ball  = __ballot_sync(0xffffffffu, nm > 0);
                unsigned multi = __ballot_sync(0xffffffffu, nm > 1);
                if (multi == 0u && __popc(ball) == 1) {
                    int src = __ffs(ball) - 1;
                    cur = (src << 2) + __shfl_sync(0xffffffffu, li, src);
                } else {
                    float lb = w0; int lj = 0;
                    bool h1 = (w1 > lb); lj = h1 ? 1 : lj; lb = h1 ? w1 : lb;
                    bool h2 = (w2 > lb); lj = h2 ? 2 : lj; lb = h2 ? w2 : lb;
                    bool h3 = (w3 > lb); lj = h3 ? 3 : lj; lb = h3 ? w3 : lb;
                    unsigned k2 = __float_as_uint(lb);
                    k2 ^= ((unsigned)((int)k2 >> 31)) | 0x80000000u;
                    cur = warp_argmax_idx(k2, lj);
                }
                if (lane == 0) tagS[t - 1] = cur;
                vrow_t = vm1; emrow_t = em1;
            }
        }
        __syncthreads();

        // ==== epilogue: decoded output + gold score + accuracy (128 thr) ====
        float sc = 0.f;
        int correct = 0;
        for (int t = k; t < TT; t += 128) {
            int tg = tagS[t];
            out[1 + b * TT + t] = (float)tg;
            int ref = __ldg(tag_ids + b * TT + t);
            if (t < len) {
                correct += (ref == tg);
                sc += __ldg(em + (long)t * KK + ref);
                if (t >= 1) {
                    int prev = __ldg(tag_ids + b * TT + t - 1);
                    sc += __ldg(g_transT + (ref << 7) + prev);   // trans[prev][ref]
                }
            }
        }
        #pragma unroll
        for (int o = 16; o > 0; o >>= 1) {
            sc      += __shfl_xor_sync(0xffffffffu, sc, o);
            correct += __shfl_xor_sync(0xffffffffu, correct, o);
        }
        if (lane == 0) { redS[0][wid] = sc; iredS[wid] = correct; }
        __syncthreads();
        if (k == 0) {
            float S = redS[0][0] + redS[0][1] + redS[0][2] + redS[0][3];
            int   C = iredS[0] + iredS[1] + iredS[2] + iredS[3];
            g_gold[b]    = S;
            g_correct[b] = C;
            g_total[b]   = len;
        }
    } else {
        // -------- CRF forward (log partition), exp-domain, t < len --------
        unsigned long long Ep[KK / 2];       // packed exp(transition) column k
        #pragma unroll
        for (int m = 0; m < KK / 2; m++)
            Ep[m] = f2pack(__expf(trans[(2 * m) * KK + k]),
                           __expf(trans[(2 * m + 1) * KK + k]));

        float alpha = em[k];
        int buf = 1;                         // first write goes to nb = 0

        float emit = em[KK + k];
        for (int t = 1; t < len; t++) {
            float emit_next = (t + 1 < TT) ? em[(t + 1) * KK + k] : 0.0f;

            float mw = alpha;
            #pragma unroll
            for (int o = 16; o > 0; o >>= 1)
                mw = fmaxf(mw, __shfl_xor_sync(0xffffffffu, mw, o));

            int nb = buf ^ 1;
            float p = __expf(alpha - mw);
            ((float*)bufP[nb])[k] = p;
            if (lane == 0) redS[nb][wid] = mw;
            __syncthreads();

            float m0 = redS[nb][0], m1 = redS[nb][1];
            float m2 = redS[nb][2], m3 = redS[nb][3];
            float m = fmaxf(fmaxf(m0, m1), fmaxf(m2, m3));

            unsigned long long acc0 = f2pack(0.f, 0.f), acc1 = acc0,
                               acc2 = acc0, acc3 = acc0;
            #pragma unroll
            for (int jj = 0; jj < 8; jj++) {
                ulonglong2 qq = bufP[nb][jj];
                acc0 = f2fma(qq.x, Ep[2 * jj],     acc0);
                acc0 = f2fma(qq.y, Ep[2 * jj + 1], acc0);
            }
            #pragma unroll
            for (int jj = 8; jj < 16; jj++) {
                ulonglong2 qq = bufP[nb][jj];
                acc1 = f2fma(qq.x, Ep[2 * jj],     acc1);
                acc1 = f2fma(qq.y, Ep[2 * jj + 1], acc1);
            }
            #pragma unroll
            for (int jj = 16; jj < 24; jj++) {
                ulonglong2 qq = bufP[nb][jj];
                acc2 = f2fma(qq.x, Ep[2 * jj],     acc2);
                acc2 = f2fma(qq.y, Ep[2 * jj + 1], acc2);
            }
            #pragma unroll
            for (int jj = 24; jj < 32; jj++) {
                ulonglong2 qq = bufP[nb][jj];
                acc3 = f2fma(qq.x, Ep[2 * jj],     acc3);
                acc3 = f2fma(qq.y, Ep[2 * jj + 1], acc3);
            }
            float lo, hi, s;
            f2unpack(acc0, lo, hi); s = __expf(m0 - m) * (lo + hi);
            f2unpack(acc1, lo, hi); s = fmaf(__expf(m1 - m), lo + hi, s);
            f2unpack(acc2, lo, hi); s = fmaf(__expf(m2 - m), lo + hi, s);
            f2unpack(acc3, lo, hi); s = fmaf(__expf(m3 - m), lo + hi, s);

            alpha = m + __logf(s) + emit;
            buf = nb;
            emit = emit_next;
        }

        // final logsumexp over k
        __syncthreads();
        float mw = alpha;
        #pragma unroll
        for (int o = 16; o > 0; o >>= 1)
            mw = fmaxf(mw, __shfl_xor_sync(0xffffffffu, mw, o));
        if (lane == 0) redS[0][wid] = mw;
        __syncthreads();
        float m = fmaxf(fmaxf(redS[0][0], redS[0][1]), fmaxf(redS[0][2], redS[0][3]));
        float p = __expf(alpha - m);
        #pragma unroll
        for (int o = 16; o > 0; o >>= 1)
            p += __shfl_xor_sync(0xffffffffu, p, o);
        __syncthreads();
        if (lane == 0) redS[0][wid] = p;
        __syncthreads();
        if (k == 0) {
            float s = redS[0][0] + redS[0][1] + redS[0][2] + redS[0][3];
            g_lognorm[b] = m + __logf(s);
        }
    }
}

// ============================================================
// Kernel 2: finalize loss + accuracy (deterministic).
// ============================================================
__global__ void crf_finalize_kernel(float* __restrict__ out)
{
    __shared__ float llS[BB];
    __shared__ int   cS[BB];
    __shared__ int   tS[BB];
    int k = threadIdx.x;   // 256 threads
    llS[k] = g_gold[k] - g_lognorm[k];
    cS[k] = g_correct[k]; tS[k] = g_total[k];
    __syncthreads();
    if (k == 0) {
        float s = 0.f; int c = 0, t = 0;
        for (int i = 0; i < BB; i++) { s += llS[i]; c += cS[i]; t += tS[i]; }
        out[0] = -s / (float)BB;
        out[1 + BB * TT] = (float)c / (float)t;
    }
}

extern "C" void kernel_launch(void* const* d_in, const int* in_sizes, int n_in,
                              void* d_out, int out_size)
{
    const float* emissions = (const float*)d_in[0];   // (256,512,128) f32
    const int*   tag_ids   = (const int*)d_in[1];     // (256,512) i32
    const int*   lengths   = (const int*)d_in[2];     // (256,) i32
    const float* trans     = (const float*)d_in[3];   // (128,128) f32
    float* out = (float*)d_out;                       // [loss, decoded(B*T), acc]

    prep_kernel<<<1 + KK, 256>>>(lengths, trans);
    crf_scan_kernel<<<2 * BB, 128>>>(emissions, tag_ids, lengths, trans, out);
    crf_finalize_kernel<<<1, BB>>>(out);
}

// round 16
// speedup vs baseline: 1.1896x; 1.1896x over previous
#include <cuda_runtime.h>

#define BB 256
#define TT 512
#define KK 128

// ---- scratch (no allocations allowed) ----
__device__ float g_v[(long)BB * TT * KK];   // 64MB: viterbi values per (b,t,k)
__device__ float g_transT[KK * KK];         // transT[c*K+j] = trans[j*K+c]
__device__ int   g_order[BB];               // batches sorted by length desc
__device__ int   g_done[BB];                // forward-complete flags (re-zeroed in prep)
__device__ float g_lognorm[BB];
__device__ float g_gold[BB];                // gold-path score (lognorm subtracted later)
__device__ int   g_correct[BB];
__device__ int   g_total[BB];

// ---- packed f32x2 helpers (sm_103a): add/fma only ----
__device__ __forceinline__ unsigned long long f2pack(float a, float b) {
    unsigned long long r;
    asm("mov.b64 %0, {%1,%2};" : "=l"(r) : "f"(a), "f"(b));
    return r;
}
__device__ __forceinline__ void f2unpack(unsigned long long v, float& a, float& b) {
    asm("mov.b64 {%0,%1}, %2;" : "=f"(a), "=f"(b) : "l"(v));
}
__device__ __forceinline__ unsigned long long f2add(unsigned long long a, unsigned long long b) {
    unsigned long long r;
    asm("add.rn.f32x2 %0, %1, %2;" : "=l"(r) : "l"(a), "l"(b));
    return r;
}
__device__ __forceinline__ unsigned long long f2fma(unsigned long long a, unsigned long long b,
                                                    unsigned long long c) {
    unsigned long long r;
    asm("fma.rn.f32x2 %0, %1, %2, %3;" : "=l"(r) : "l"(a), "l"(b), "l"(c));
    return r;
}

// warp argmax over (packed 4-per-lane) candidates: returns global index 0..127.
__device__ __forceinline__ int warp_argmax_idx(unsigned key, int bi)
{
    unsigned mx = key;
    #pragma unroll
    for (int o = 16; o > 0; o >>= 1) {           // shfl butterfly max
        unsigned ok = __shfl_xor_sync(0xffffffffu, mx, o);
        mx = (ok > mx) ? ok : mx;
    }
    unsigned ball = __ballot_sync(0xffffffffu, key == mx);
    int src = __ffs(ball) - 1;
    return (src << 2) + __shfl_sync(0xffffffffu, bi, src);
}

// ============================================================
// Kernel 0: prep = LPT sort + flag reset (block 0),
//           transpose (blocks 1..128).
// ============================================================
__global__ __launch_bounds__(256)
void prep_kernel(const int* __restrict__ lengths, const float* __restrict__ trans)
{
    if (blockIdx.x == 0) {
        __shared__ int keys[BB];
        int b = threadIdx.x;
        g_done[b] = 0;                                   // reset flags each replay
        int key = (lengths[b] << 8) | (BB - 1 - b);
        keys[b] = key;
        __syncthreads();
        int r = 0;
        #pragma unroll 8
        for (int j = 0; j < BB; j++) r += (keys[j] > key);
        g_order[r] = b;
    } else {
        int c = blockIdx.x - 1;
        int j = threadIdx.x;
        if (j < KK) g_transT[c * KK + j] = trans[j * KK + c];
    }
}

// ============================================================
// Kernel 1: 768 blocks.
//  [0,256):   Viterbi forward (values only) -> fence -> flag.
//  [256,512): CRF forward (exp-domain logsumexp).
//  [512,768): spin-wait on flag, then chase + epilogue.
// ============================================================
__global__ __launch_bounds__(128)
void crf_scan_kernel(const float* __restrict__ emissions,
                     const int*   __restrict__ tag_ids,
                     const int*   __restrict__ lengths,
                     const float* __restrict__ trans,
                     float*       __restrict__ out)
{
    __shared__ ulonglong2 bufP[2][KK / 4];   // packed state vector (double buffer)
    __shared__ float      redS[2][4];
    __shared__ int        tagS[TT];
    __shared__ int        iredS[4];

    const int k    = threadIdx.x;
    const int role = blockIdx.x >> 8;                    // 0, 1, 2
    const int b    = g_order[blockIdx.x & (BB - 1)];
    const int len  = lengths[b];
    const float* em = emissions + (long)b * TT * KK;
    const int wid = k >> 5, lane = k & 31;

    if (role == 0) {
        // -------- Viterbi forward: packed adds, scalar max, t < len --------
        unsigned long long trp[KK / 2];      // packed transition column k
        #pragma unroll
        for (int m = 0; m < KK / 2; m++)
            trp[m] = f2pack(trans[(2 * m) * KK + k], trans[(2 * m + 1) * KK + k]);

        float* vglob = g_v + (long)b * TT * KK;

        float v = em[k];                     // t = 0
        vglob[k] = v;
        int buf = 0;
        ((float*)bufP[0])[k] = v;
        __syncthreads();

        float emit = em[KK + k];             // prefetch t = 1
        for (int t = 1; t < len; t++) {
            float emit_next = (t + 1 < TT) ? em[(t + 1) * KK + k] : 0.0f;

            float b0 = -3.4e38f, b1 = -3.4e38f, b2 = -3.4e38f, b3 = -3.4e38f;
            #pragma unroll
            for (int jj = 0; jj < KK / 4; jj++) {
                ulonglong2 q = bufP[buf][jj];
                float x0, x1, x2, x3;
                f2unpack(f2add(q.x, trp[2 * jj]),     x0, x1);
                f2unpack(f2add(q.y, trp[2 * jj + 1]), x2, x3);
                b0 = fmaxf(b0, x0); b1 = fmaxf(b1, x1);
                b2 = fmaxf(b2, x2); b3 = fmaxf(b3, x3);
            }
            v = fmaxf(fmaxf(b0, b1), fmaxf(b2, b3)) + emit;
            vglob[t * KK + k] = v;

            ((float*)bufP[buf ^ 1])[k] = v;
            __syncthreads();
            buf ^= 1;
            emit = emit_next;
        }
        __syncthreads();
        if (k == 0) {
            __threadfence();                 // make g_v visible device-wide
            g_done[b] = 1;
        }
    } else if (role == 1) {
        // -------- CRF forward (log partition), exp-domain, t < len --------
        unsigned long long Ep[KK / 2];       // packed exp(transition) column k
        #pragma unroll
        for (int m = 0; m < KK / 2; m++)
            Ep[m] = f2pack(__expf(trans[(2 * m) * KK + k]),
                           __expf(trans[(2 * m + 1) * KK + k]));

        float alpha = em[k];
        int buf = 1;                         // first write goes to nb = 0

        float emit = em[KK + k];
        for (int t = 1; t < len; t++) {
            float emit_next = (t + 1 < TT) ? em[(t + 1) * KK + k] : 0.0f;

            float mw = alpha;
            #pragma unroll
            for (int o = 16; o > 0; o >>= 1)
                mw = fmaxf(mw, __shfl_xor_sync(0xffffffffu, mw, o));

            int nb = buf ^ 1;
            float p = __expf(alpha - mw);
            ((float*)bufP[nb])[k] = p;
            if (lane == 0) redS[nb][wid] = mw;
            __syncthreads();

            float m0 = redS[nb][0], m1 = redS[nb][1];
            float m2 = redS[nb][2], m3 = redS[nb][3];
            float m = fmaxf(fmaxf(m0, m1), fmaxf(m2, m3));

            unsigned long long acc0 = f2pack(0.f, 0.f), acc1 = acc0,
                               acc2 = acc0, acc3 = acc0;
            #pragma unroll
            for (int jj = 0; jj < 8; jj++) {
                ulonglong2 qq = bufP[nb][jj];
                acc0 = f2fma(qq.x, Ep[2 * jj],     acc0);
                acc0 = f2fma(qq.y, Ep[2 * jj + 1], acc0);
            }
            #pragma unroll
            for (int jj = 8; jj < 16; jj++) {
                ulonglong2 qq = bufP[nb][jj];
                acc1 = f2fma(qq.x, Ep[2 * jj],     acc1);
                acc1 = f2fma(qq.y, Ep[2 * jj + 1], acc1);
            }
            #pragma unroll
            for (int jj = 16; jj < 24; jj++) {
                ulonglong2 qq = bufP[nb][jj];
                acc2 = f2fma(qq.x, Ep[2 * jj],     acc2);
                acc2 = f2fma(qq.y, Ep[2 * jj + 1], acc2);
            }
            #pragma unroll
            for (int jj = 24; jj < 32; jj++) {
                ulonglong2 qq = bufP[nb][jj];
                acc3 = f2fma(qq.x, Ep[2 * jj],     acc3);
                acc3 = f2fma(qq.y, Ep[2 * jj + 1], acc3);
            }
            float lo, hi, s;
            f2unpack(acc0, lo, hi); s = __expf(m0 - m) * (lo + hi);
            f2unpack(acc1, lo, hi); s = fmaf(__expf(m1 - m), lo + hi, s);
            f2unpack(acc2, lo, hi); s = fmaf(__expf(m2 - m), lo + hi, s);
            f2unpack(acc3, lo, hi); s = fmaf(__expf(m3 - m), lo + hi, s);

            alpha = m + __logf(s) + emit;
            buf = nb;
            emit = emit_next;
        }

        // final logsumexp over k
        __syncthreads();
        float mw = alpha;
        #pragma unroll
        for (int o = 16; o > 0; o >>= 1)
            mw = fmaxf(mw, __shfl_xor_sync(0xffffffffu, mw, o));
        if (lane == 0) redS[0][wid] = mw;
        __syncthreads();
        float m = fmaxf(fmaxf(redS[0][0], redS[0][1]), fmaxf(redS[0][2], redS[0][3]));
        float p = __expf(alpha - m);
        #pragma unroll
        for (int o = 16; o > 0; o >>= 1)
            p += __shfl_xor_sync(0xffffffffu, p, o);
        __syncthreads();
        if (lane == 0) redS[0][wid] = p;
        __syncthreads();
        if (k == 0) {
            float s = redS[0][0] + redS[0][1] + redS[0][2] + redS[0][3];
            g_lognorm[b] = m + __logf(s);
        }
    } else {
        // -------- chase block: wait for forward b, then backtrack --------
        if (k == 0) {
            volatile int* flag = &g_done[b];
            while (*flag == 0) __nanosleep(200);
        }
        __syncthreads();

        const int t0 = len - 1;
        const float* vb = g_v + (long)b * TT * KK;

        if (wid == 0) {
            // warm transT into L1 (independent float4 loads)
            float wsum = 0.f;
            const float4* tT4 = (const float4*)g_transT;
            #pragma unroll 4
            for (int i = lane; i < KK * KK / 4; i += 32) {
                float4 w4 = __ldg(tT4 + i);
                wsum += w4.x + w4.y + w4.z + w4.w;
            }

            // last_tag = argmax of final row
            float4 q = __ldg((const float4*)(vb + (long)t0 * KK) + lane);
            float bv = q.x; int bi = 0;
            bool s1 = (q.y > bv); bi = s1 ? 1 : bi; bv = s1 ? q.y : bv;
            bool s2 = (q.z > bv); bi = s2 ? 2 : bi; bv = s2 ? q.z : bv;
            bool s3 = (q.w > bv); bi = s3 ? 3 : bi; bv = s3 ? q.w : bv;
            unsigned key = __float_as_uint(bv);
            key ^= ((unsigned)((int)key >> 31)) | 0x80000000u;
            if (wsum == -1.2345e38f) key = 0;        // keep warm loads alive
            int cur = warp_argmax_idx(key, bi);

            // tail fill [t0, TT)
            for (int t = t0 + lane; t < TT; t += 32) tagS[t] = cur;

            // prefetch ring depth 4: ring[u] = row (t-1-u)
            float4 ring[4];
            #pragma unroll
            for (int u = 0; u < 4; u++) {
                int r = t0 - 1 - u; r = (r > 0) ? r : 0;
                ring[u] = __ldcs((const float4*)(vb + (long)r * KK) + lane);
            }

            int t = t0;
            while (t >= 5) {
                #pragma unroll
                for (int u = 0; u < 4; u++) {
                    float4 vrow = ring[u];
                    int nr = t - 5 - u; nr = (nr > 0) ? nr : 0;
                    ring[u] = __ldcs((const float4*)(vb + (long)nr * KK) + lane);

                    float4 tc4 = __ldg((const float4*)(g_transT + (cur << 7)) + lane);
                    float w0 = vrow.x + tc4.x, w1 = vrow.y + tc4.y;
                    float w2 = vrow.z + tc4.z, w3 = vrow.w + tc4.w;
                    float lb = w0; int li = 0;
                    bool h1 = (w1 > lb); li = h1 ? 1 : li; lb = h1 ? w1 : lb;
                    bool h2 = (w2 > lb); li = h2 ? 2 : li; lb = h2 ? w2 : lb;
                    bool h3 = (w3 > lb); li = h3 ? 3 : li; lb = h3 ? w3 : lb;
                    unsigned k2 = __float_as_uint(lb);
                    k2 ^= ((unsigned)((int)k2 >> 31)) | 0x80000000u;
                    cur = warp_argmax_idx(k2, li);
                    if (lane == 0) tagS[t - u - 1] = cur;
                }
                t -= 4;
            }
            for (; t >= 1; t--) {
                float4 vrow = __ldcs((const float4*)(vb + (long)(t - 1) * KK) + lane);
                float4 tc4 = __ldg((const float4*)(g_transT + (cur << 7)) + lane);
                float w0 = vrow.x + tc4.x, w1 = vrow.y + tc4.y;
                float w2 = vrow.z + tc4.z, w3 = vrow.w + tc4.w;
                float lb = w0; int li = 0;
                bool h1 = (w1 > lb); li = h1 ? 1 : li; lb = h1 ? w1 : lb;
                bool h2 = (w2 > lb); li = h2 ? 2 : li; lb = h2 ? w2 : lb;
                bool h3 = (w3 > lb); li = h3 ? 3 : li; lb = h3 ? w3 : lb;
                unsigned k2 = __float_as_uint(lb);
                k2 ^= ((unsigned)((int)k2 >> 31)) | 0x80000000u;
                cur = warp_argmax_idx(k2, li);
                if (lane == 0) tagS[t - 1] = cur;
            }
        }
        __syncthreads();

        // ==== epilogue: decoded output + gold score + accuracy (128 thr) ====
        float sc = 0.f;
        int correct = 0;
        for (int t = k; t < TT; t += 128) {
            int tg = tagS[t];
            out[1 + b * TT + t] = (float)tg;
            int ref = __ldg(tag_ids + b * TT + t);
            if (t < len) {
                correct += (ref == tg);
                sc += __ldg(em + (long)t * KK + ref);
                if (t >= 1) {
                    int prev = __ldg(tag_ids + b * TT + t - 1);
                    sc += __ldg(g_transT + (ref << 7) + prev);   // trans[prev][ref]
                }
            }
        }
        #pragma unroll
        for (int o = 16; o > 0; o >>= 1) {
            sc      += __shfl_xor_sync(0xffffffffu, sc, o);
            correct += __shfl_xor_sync(0xffffffffu, correct, o);
        }
        if (lane == 0) { redS[0][wid] = sc; iredS[wid] = correct; }
        __syncthreads();
        if (k == 0) {
            float S = redS[0][0] + redS[0][1] + redS[0][2] + redS[0][3];
            int   C = iredS[0] + iredS[1] + iredS[2] + iredS[3];
            g_gold[b]    = S;
            g_correct[b] = C;
            g_total[b]   = len;
        }
    }
}

// ============================================================
// Kernel 2: finalize loss + accuracy (deterministic).
// ============================================================
__global__ void crf_finalize_kernel(float* __restrict__ out)
{
    __shared__ float llS[BB];
    __shared__ int   cS[BB];
    __shared__ int   tS[BB];
    int k = threadIdx.x;   // 256 threads
    llS[k] = g_gold[k] - g_lognorm[k];
    cS[k] = g_correct[k]; tS[k] = g_total[k];
    __syncthreads();
    if (k == 0) {
        float s = 0.f; int c = 0, t = 0;
        for (int i = 0; i < BB; i++) { s += llS[i]; c += cS[i]; t += tS[i]; }
        out[0] = -s / (float)BB;
        out[1 + BB * TT] = (float)c / (float)t;
    }
}

extern "C" void kernel_launch(void* const* d_in, const int* in_sizes, int n_in,
                              void* d_out, int out_size)
{
    const float* emissions = (const float*)d_in[0];   // (256,512,128) f32
    const int*   tag_ids   = (const int*)d_in[1];     // (256,512) i32
    const int*   lengths   = (const int*)d_in[2];     // (256,) i32
    const float* trans     = (const float*)d_in[3];   // (128,128) f32
    float* out = (float*)d_out;                       // [loss, decoded(B*T), acc]

    prep_kernel<<<1 + KK, 256>>>(lengths, trans);
    crf_scan_kernel<<<3 * BB, 128>>>(emissions, tag_ids, lengths, trans, out);
    crf_finalize_kernel<<<1, BB>>>(out);
}

// round 17
// speedup vs baseline: 1.2159x; 1.0221x over previous
#include <cuda_runtime.h>

#define BB 256
#define TT 512
#define KK 128

// ---- scratch (no allocations allowed) ----
__device__ float g_v[(long)BB * TT * KK];   // 64MB: viterbi values per (b,t,k)
__device__ float g_transT[KK * KK];         // transT[c*K+j] = trans[j*K+c]
__device__ int   g_order[BB];               // batches sorted by length desc
__device__ float g_lognorm[BB];
__device__ float g_gold[BB];                // gold-path score (lognorm subtracted later)
__device__ int   g_correct[BB];
__device__ int   g_total[BB];

// ---- packed f32x2 helpers (sm_103a): add/fma only ----
__device__ __forceinline__ unsigned long long f2pack(float a, float b) {
    unsigned long long r;
    asm("mov.b64 %0, {%1,%2};" : "=l"(r) : "f"(a), "f"(b));
    return r;
}
__device__ __forceinline__ void f2unpack(unsigned long long v, float& a, float& b) {
    asm("mov.b64 {%0,%1}, %2;" : "=f"(a), "=f"(b) : "l"(v));
}
__device__ __forceinline__ unsigned long long f2add(unsigned long long a, unsigned long long b) {
    unsigned long long r;
    asm("add.rn.f32x2 %0, %1, %2;" : "=l"(r) : "l"(a), "l"(b));
    return r;
}
__device__ __forceinline__ unsigned long long f2fma(unsigned long long a, unsigned long long b,
                                                    unsigned long long c) {
    unsigned long long r;
    asm("fma.rn.f32x2 %0, %1, %2, %3;" : "=l"(r) : "l"(a), "l"(b), "l"(c));
    return r;
}

// ordered-uint map: monotone with float order
__device__ __forceinline__ unsigned fkey(float f) {
    unsigned u = __float_as_uint(f);
    return u ^ (((unsigned)((int)u >> 31)) | 0x80000000u);
}

// single-collective warp argmax over 4 candidates/lane.
// carries (value_key:32 | (127-idx):32) through one u64 butterfly;
// equal values -> larger (127-idx) -> smaller idx (first-index tie-break).
__device__ __forceinline__ int warp_argmax64(float w0, float w1, float w2, float w3, int lane)
{
    int base = lane << 2;
    unsigned long long c0 = ((unsigned long long)fkey(w0) << 32) | (unsigned)(127 - (base + 0));
    unsigned long long c1 = ((unsigned long long)fkey(w1) << 32) | (unsigned)(127 - (base + 1));
    unsigned long long c2 = ((unsigned long long)fkey(w2) << 32) | (unsigned)(127 - (base + 2));
    unsigned long long c3 = ((unsigned long long)fkey(w3) << 32) | (unsigned)(127 - (base + 3));
    unsigned long long a = (c1 > c0) ? c1 : c0;
    unsigned long long b = (c3 > c2) ? c3 : c2;
    unsigned long long m = (b > a) ? b : a;
    #pragma unroll
    for (int o = 16; o > 0; o >>= 1) {
        unsigned long long q = __shfl_xor_sync(0xffffffffu, m, o);
        m = (q > m) ? q : m;
    }
    return 127 - (int)(m & 0xffu);           // uniform across lanes
}

// ============================================================
// Kernel 0: prep = LPT sort (block 0) + transpose (blocks 1..128).
// ============================================================
__global__ __launch_bounds__(256)
void prep_kernel(const int* __restrict__ lengths, const float* __restrict__ trans)
{
    if (blockIdx.x == 0) {
        __shared__ int keys[BB];
        int b = threadIdx.x;
        int key = (lengths[b] << 8) | (BB - 1 - b);
        keys[b] = key;
        __syncthreads();
        int r = 0;
        #pragma unroll 8
        for (int j = 0; j < BB; j++) r += (keys[j] > key);
        g_order[r] = b;
    } else {
        int c = blockIdx.x - 1;
        int j = threadIdx.x;
        if (j < KK) g_transT[c * KK + j] = trans[j * KK + c];
    }
}

// ============================================================
// Kernel 1: fused scans + backtrack, early exit at t = len.
// Blocks [0,256): Viterbi forward THEN warp-0 chase (u64
// single-butterfly argmax) THEN epilogue.
// Blocks [256,512): CRF forward (exp-domain logsumexp).
// ============================================================
__global__ __launch_bounds__(128)
void crf_scan_kernel(const float* __restrict__ emissions,
                     const int*   __restrict__ tag_ids,
                     const int*   __restrict__ lengths,
                     const float* __restrict__ trans,
                     float*       __restrict__ out)
{
    __shared__ ulonglong2 bufP[2][KK / 4];   // packed state vector (double buffer)
    __shared__ float      redS[2][4];
    __shared__ int        tagS[TT];
    __shared__ int        iredS[4];

    const int k    = threadIdx.x;
    const int role = (blockIdx.x >= BB);
    const int b    = g_order[blockIdx.x & (BB - 1)];
    const int len  = lengths[b];
    const float* em = emissions + (long)b * TT * KK;
    const int wid = k >> 5, lane = k & 31;

    if (!role) {
        // -------- Viterbi forward: packed adds, scalar max, t < len --------
        unsigned long long trp[KK / 2];      // packed transition column k
        #pragma unroll
        for (int m = 0; m < KK / 2; m++)
            trp[m] = f2pack(trans[(2 * m) * KK + k], trans[(2 * m + 1) * KK + k]);

        float* vglob = g_v + (long)b * TT * KK;

        float v = em[k];                     // t = 0
        vglob[k] = v;
        int buf = 0;
        ((float*)bufP[0])[k] = v;
        __syncthreads();

        float emit = em[KK + k];             // prefetch t = 1
        for (int t = 1; t < len; t++) {
            float emit_next = (t + 1 < TT) ? em[(t + 1) * KK + k] : 0.0f;

            float b0 = -3.4e38f, b1 = -3.4e38f, b2 = -3.4e38f, b3 = -3.4e38f;
            #pragma unroll
            for (int jj = 0; jj < KK / 4; jj++) {
                ulonglong2 q = bufP[buf][jj];
                float x0, x1, x2, x3;
                f2unpack(f2add(q.x, trp[2 * jj]),     x0, x1);
                f2unpack(f2add(q.y, trp[2 * jj + 1]), x2, x3);
                b0 = fmaxf(b0, x0); b1 = fmaxf(b1, x1);
                b2 = fmaxf(b2, x2); b3 = fmaxf(b3, x3);
            }
            v = fmaxf(fmaxf(b0, b1), fmaxf(b2, b3)) + emit;
            vglob[t * KK + k] = v;

            ((float*)bufP[buf ^ 1])[k] = v;
            __syncthreads();
            buf ^= 1;
            emit = emit_next;
        }

        // ==== backtrack chase (warp 0): u64-butterfly argmax ====
        if (wid == 0) {
            const int t0 = len - 1;
            const float* vb = vglob;

            // warm transT into L1 (independent float4 loads)
            float wsum = 0.f;
            const float4* tT4 = (const float4*)g_transT;
            #pragma unroll 4
            for (int i = lane; i < KK * KK / 4; i += 32) {
                float4 w4 = __ldg(tT4 + i);
                wsum += w4.x + w4.y + w4.z + w4.w;
            }

            // last_tag = argmax of final row (in smem bufP[buf])
            float4 q = ((const float4*)bufP[buf])[lane];
            float qx = (wsum == -1.2345e38f) ? 0.f : q.x;    // keep warm loads alive
            int cur = warp_argmax64(qx, q.y, q.z, q.w, lane);

            // tail fill [t0, TT)
            for (int t = t0 + lane; t < TT; t += 32) tagS[t] = cur;

            // prefetch ring depth 4: ring[u] = row (t-1-u)
            float4 ring[4];
            #pragma unroll
            for (int u = 0; u < 4; u++) {
                int r = t0 - 1 - u; r = (r > 0) ? r : 0;
                ring[u] = __ldcs((const float4*)(vb + (long)r * KK) + lane);
            }

            int t = t0;
            while (t >= 5) {
                #pragma unroll
                for (int u = 0; u < 4; u++) {
                    float4 vrow = ring[u];
                    int nr = t - 5 - u; nr = (nr > 0) ? nr : 0;
                    ring[u] = __ldcs((const float4*)(vb + (long)nr * KK) + lane);

                    float4 tc4 = __ldg((const float4*)(g_transT + (cur << 7)) + lane);
                    cur = warp_argmax64(vrow.x + tc4.x, vrow.y + tc4.y,
                                        vrow.z + tc4.z, vrow.w + tc4.w, lane);
                    if (lane == 0) tagS[t - u - 1] = cur;
                }
                t -= 4;
            }
            for (; t >= 1; t--) {
                float4 vrow = __ldcs((const float4*)(vb + (long)(t - 1) * KK) + lane);
                float4 tc4 = __ldg((const float4*)(g_transT + (cur << 7)) + lane);
                cur = warp_argmax64(vrow.x + tc4.x, vrow.y + tc4.y,
                                    vrow.z + tc4.z, vrow.w + tc4.w, lane);
                if (lane == 0) tagS[t - 1] = cur;
            }
        }
        __syncthreads();

        // ==== epilogue: decoded output + gold score + accuracy (128 thr) ====
        float sc = 0.f;
        int correct = 0;
        for (int t = k; t < TT; t += 128) {
            int tg = tagS[t];
            out[1 + b * TT + t] = (float)tg;
            int ref = __ldg(tag_ids + b * TT + t);
            if (t < len) {
                correct += (ref == tg);
                sc += __ldg(em + (long)t * KK + ref);
                if (t >= 1) {
                    int prev = __ldg(tag_ids + b * TT + t - 1);
                    sc += __ldg(g_transT + (ref << 7) + prev);   // trans[prev][ref]
                }
            }
        }
        #pragma unroll
        for (int o = 16; o > 0; o >>= 1) {
            sc      += __shfl_xor_sync(0xffffffffu, sc, o);
            correct += __shfl_xor_sync(0xffffffffu, correct, o);
        }
        if (lane == 0) { redS[0][wid] = sc; iredS[wid] = correct; }
        __syncthreads();
        if (k == 0) {
            float S = redS[0][0] + redS[0][1] + redS[0][2] + redS[0][3];
            int   C = iredS[0] + iredS[1] + iredS[2] + iredS[3];
            g_gold[b]    = S;
            g_correct[b] = C;
            g_total[b]   = len;
        }
    } else {
        // -------- CRF forward (log partition), exp-domain, t < len --------
        unsigned long long Ep[KK / 2];       // packed exp(transition) column k
        #pragma unroll
        for (int m = 0; m < KK / 2; m++)
            Ep[m] = f2pack(__expf(trans[(2 * m) * KK + k]),
                           __expf(trans[(2 * m + 1) * KK + k]));

        float alpha = em[k];
        int buf = 1;                         // first write goes to nb = 0

        float emit = em[KK + k];
        for (int t = 1; t < len; t++) {
            float emit_next = (t + 1 < TT) ? em[(t + 1) * KK + k] : 0.0f;

            float mw = alpha;
            #pragma unroll
            for (int o = 16; o > 0; o >>= 1)
                mw = fmaxf(mw, __shfl_xor_sync(0xffffffffu, mw, o));

            int nb = buf ^ 1;
            float p = __expf(alpha - mw);
            ((float*)bufP[nb])[k] = p;
            if (lane == 0) redS[nb][wid] = mw;
            __syncthreads();

            float m0 = redS[nb][0], m1 = redS[nb][1];
            float m2 = redS[nb][2], m3 = redS[nb][3];
            float m = fmaxf(fmaxf(m0, m1), fmaxf(m2, m3));

            unsigned long long acc0 = f2pack(0.f, 0.f), acc1 = acc0,
                               acc2 = acc0, acc3 = acc0;
            #pragma unroll
            for (int jj = 0; jj < 8; jj++) {
                ulonglong2 qq = bufP[nb][jj];
                acc0 = f2fma(qq.x, Ep[2 * jj],     acc0);
                acc0 = f2fma(qq.y, Ep[2 * jj + 1], acc0);
            }
            #pragma unroll
            for (int jj = 8; jj < 16; jj++) {
                ulonglong2 qq = bufP[nb][jj];
                acc1 = f2fma(qq.x, Ep[2 * jj],     acc1);
                acc1 = f2fma(qq.y, Ep[2 * jj + 1], acc1);
            }
            #pragma unroll
            for (int jj = 16; jj < 24; jj++) {
                ulonglong2 qq = bufP[nb][jj];
                acc2 = f2fma(qq.x, Ep[2 * jj],     acc2);
                acc2 = f2fma(qq.y, Ep[2 * jj + 1], acc2);
            }
            #pragma unroll
            for (int jj = 24; jj < 32; jj++) {
                ulonglong2 qq = bufP[nb][jj];
                acc3 = f2fma(qq.x, Ep[2 * jj],     acc3);
                acc3 = f2fma(qq.y, Ep[2 * jj + 1], acc3);
            }
            float lo, hi, s;
            f2unpack(acc0, lo, hi); s = __expf(m0 - m) * (lo + hi);
            f2unpack(acc1, lo, hi); s = fmaf(__expf(m1 - m), lo + hi, s);
            f2unpack(acc2, lo, hi); s = fmaf(__expf(m2 - m), lo + hi, s);
            f2unpack(acc3, lo, hi); s = fmaf(__expf(m3 - m), lo + hi, s);

            alpha = m + __logf(s) + emit;
            buf = nb;
            emit = emit_next;
        }

        // final logsumexp over k
        __syncthreads();
        float mw = alpha;
        #pragma unroll
        for (int o = 16; o > 0; o >>= 1)
            mw = fmaxf(mw, __shfl_xor_sync(0xffffffffu, mw, o));
        if (lane == 0) redS[0][wid] = mw;
        __syncthreads();
        float m = fmaxf(fmaxf(redS[0][0], redS[0][1]), fmaxf(redS[0][2], redS[0][3]));
        float p = __expf(alpha - m);
        #pragma unroll
        for (int o = 16; o > 0; o >>= 1)
            p += __shfl_xor_sync(0xffffffffu, p, o);
        __syncthreads();
        if (lane == 0) redS[0][wid] = p;
        __syncthreads();
        if (k == 0) {
            float s = redS[0][0] + redS[0][1] + redS[0][2] + redS[0][3];
            g_lognorm[b] = m + __logf(s);
        }
    }
}

// ============================================================
// Kernel 2: finalize loss + accuracy (deterministic).
// ============================================================
__global__ void crf_finalize_kernel(float* __restrict__ out)
{
    __shared__ float llS[BB];
    __shared__ int   cS[BB];
    __shared__ int   tS[BB];
    int k = threadIdx.x;   // 256 threads
    llS[k] = g_gold[k] - g_lognorm[k];
    cS[k] = g_correct[k]; tS[k] = g_total[k];
    __syncthreads();
    if (k == 0) {
        float s = 0.f; int c = 0, t = 0;
        for (int i = 0; i < BB; i++) { s += llS[i]; c += cS[i]; t += tS[i]; }
        out[0] = -s / (float)BB;
        out[1 + BB * TT] = (float)c / (float)t;
    }
}

extern "C" void kernel_launch(void* const* d_in, const int* in_sizes, int n_in,
                              void* d_out, int out_size)
{
    const float* emissions = (const float*)d_in[0];   // (256,512,128) f32
    const int*   tag_ids   = (const int*)d_in[1];     // (256,512) i32
    const int*   lengths   = (const int*)d_in[2];     // (256,) i32
    const float* trans     = (const float*)d_in[3];   // (128,128) f32
    float* out = (float*)d_out;                       // [loss, decoded(B*T), acc]

    prep_kernel<<<1 + KK, 256>>>(lengths, trans);
    crf_scan_kernel<<<2 * BB, 128>>>(emissions, tag_ids, lengths, trans, out);
    crf_finalize_kernel<<<1, BB>>>(out);
}